// round 16
// baseline (speedup 1.0000x reference)
#include <cuda_runtime.h>
#include <cuda_fp16.h>
#include <cstdint>
#include <math.h>

#define BATCH 8
#define NN    2048
#define FF    256
#define OO    256
#define ROWS  (BATCH*NN)   /* 16384 */

// GEMM tiling: 128x128 CTA tile, K-step 64, 256 threads, fp16, 3-stage, 2 CTAs/SM
#define BM 128
#define BN 128
#define BK 64
#define NTH 256
#define APADH 72
#define BPADH 72
#define A_TILE_H (BM*APADH)
#define B_TILE_H (BN*BPADH)
#define NSTAGE 3
#define SMEM_BYTES (NSTAGE*(A_TILE_H+B_TILE_H)*2)   /* 110592 B */

// ---------------- scratch ----------------
__device__ float  g_rs  [ROWS];
__device__ float  g_cs  [ROWS];
__device__ __half g_adjh[(size_t)BATCH*NN*NN];
__device__ __half g_xnh [ROWS*FF];
__device__ __half g_xshT[ROWS*FF];       // [b][f][n]
__device__ __half g_zh  [ROWS*FF];
__device__ __half g_wT  [2*FF*OO];       // [0]=(Ws+Wn)^T, [1]=Wn^T, [o][k]

// ---------------- helpers ----------------
__device__ __forceinline__ uint32_t h2u(__half2 h) {
    return *reinterpret_cast<uint32_t*>(&h);
}
__device__ __forceinline__ float softplus_f(float x) {
    return fmaxf(x, 0.0f) + log1pf(expf(-fabsf(x)));
}
__device__ __forceinline__ void cp16(uint32_t dst, const void* src) {
    asm volatile("cp.async.cg.shared.global [%0], [%1], 16;\n" :: "r"(dst), "l"(src));
}
#define CP_COMMIT() asm volatile("cp.async.commit_group;\n" ::: "memory")
#define CP_WAIT(n)  asm volatile("cp.async.wait_group %0;\n" :: "n"(n) : "memory")

__device__ __forceinline__ void mma_f16(float (&d)[4], const uint32_t (&a)[4], const uint32_t (&b)[2]) {
    asm volatile(
        "mma.sync.aligned.m16n8k16.row.col.f32.f16.f16.f32 "
        "{%0,%1,%2,%3}, {%4,%5,%6,%7}, {%8,%9}, {%0,%1,%2,%3};\n"
        : "+f"(d[0]), "+f"(d[1]), "+f"(d[2]), "+f"(d[3])
        : "r"(a[0]), "r"(a[1]), "r"(a[2]), "r"(a[3]), "r"(b[0]), "r"(b[1]));
}
__device__ __forceinline__ void ldsm4(uint32_t (&r)[4], uint32_t addr) {
    asm volatile("ldmatrix.sync.aligned.m8n8.x4.shared.b16 {%0,%1,%2,%3}, [%4];"
                 : "=r"(r[0]), "=r"(r[1]), "=r"(r[2]), "=r"(r[3]) : "r"(addr));
}
__device__ __forceinline__ float4 ldcs4(const float* p) {
    float4 v;
    asm volatile("ld.global.cs.v4.f32 {%0,%1,%2,%3}, [%4];"
                 : "=f"(v.x), "=f"(v.y), "=f"(v.z), "=f"(v.w) : "l"(p));
    return v;
}
__device__ __forceinline__ void stcs2(__half* p, uint32_t a, uint32_t b) {
    asm volatile("st.global.cs.v2.b32 [%0], {%1,%2};" :: "l"(p), "r"(a), "r"(b));
}

// ---------------- fused prep: zero g_cs + transpose weights ----------------
__global__ void __launch_bounds__(256) prep_kernel(const float* __restrict__ Ws,
                                                   const float* __restrict__ Wn) {
    if (blockIdx.x < 64) {
        g_cs[blockIdx.x * 256 + threadIdx.x] = 0.f;
        return;
    }
    __shared__ float t1[32][33], t2[32][33];
    int bid = blockIdx.x - 64;                 // 0..63
    int tx = threadIdx.x & 31, ty = threadIdx.x >> 5;
    int k0 = (bid & 7) * 32, o0 = (bid >> 3) * 32;
#pragma unroll
    for (int i = 0; i < 4; i++) {
        int k = k0 + ty + i * 8;
        float wn = Wn[(size_t)k * OO + o0 + tx];
        float ws = Ws[(size_t)k * OO + o0 + tx];
        t1[ty + i * 8][tx] = ws + wn;
        t2[ty + i * 8][tx] = wn;
    }
    __syncthreads();
#pragma unroll
    for (int i = 0; i < 4; i++) {
        int o = o0 + ty + i * 8;
        g_wT[(size_t)o * FF + k0 + tx]           = __float2half_rn(t1[tx][ty + i * 8]);
        g_wT[FF * OO + (size_t)o * FF + k0 + tx] = __float2half_rn(t2[tx][ty + i * 8]);
    }
}

// ---------------- fused degree + fp16-convert: 8 rows/block, 2048 blocks ----------------
__global__ void __launch_bounds__(256) degree_kernel(const float* __restrict__ adj) {
    __shared__ float rowpart[8][9];
    int tid = threadIdx.x, lane = tid & 31, w = tid >> 5;
    size_t r0 = (size_t)blockIdx.x * 8;
    const float* base = adj + r0 * NN;
    int c0 = tid * 4;

    float cs[8] = {0,0,0,0,0,0,0,0};
#pragma unroll
    for (int rr = 0; rr < 8; rr++) {
        float4 v0 = ldcs4(base + (size_t)rr * NN + c0);
        float4 v1 = ldcs4(base + (size_t)rr * NN + c0 + 1024);
        __half2 h0 = __floats2half2_rn(v0.x, v0.y);
        __half2 h1 = __floats2half2_rn(v0.z, v0.w);
        __half2 h2 = __floats2half2_rn(v1.x, v1.y);
        __half2 h3 = __floats2half2_rn(v1.z, v1.w);
        __half* hd = g_adjh + (r0 + rr) * NN;
        stcs2(hd + c0,        h2u(h0), h2u(h1));
        stcs2(hd + c0 + 1024, h2u(h2), h2u(h3));

        cs[0] += v0.x; cs[1] += v0.y; cs[2] += v0.z; cs[3] += v0.w;
        cs[4] += v1.x; cs[5] += v1.y; cs[6] += v1.z; cs[7] += v1.w;
        float rs = v0.x + v0.y + v0.z + v0.w + v1.x + v1.y + v1.z + v1.w;
#pragma unroll
        for (int off = 16; off > 0; off >>= 1) rs += __shfl_xor_sync(0xffffffffu, rs, off);
        if (lane == 0) rowpart[rr][w] = rs;
    }
    __syncthreads();
    if (tid < 8) {
        float s = 0.f;
#pragma unroll
        for (int j = 0; j < 8; j++) s += rowpart[tid][j];
        g_rs[r0 + tid] = s;
    }
    int b = (int)(r0 >> 11);
    float* cbase = g_cs + (size_t)b * NN;
#pragma unroll
    for (int j = 0; j < 4; j++) atomicAdd(cbase + c0 + j, cs[j]);
#pragma unroll
    for (int j = 0; j < 4; j++) atomicAdd(cbase + c0 + 1024 + j, cs[4 + j]);
}

// ---------------- layernorm (32 rows/block; coalesced transposed write) ----------------
__global__ void __launch_bounds__(256) ln_kernel(const float* __restrict__ x,
                                                 const float* __restrict__ gamma,
                                                 const float* __restrict__ beta) {
    __shared__ float tr[256 * 37];
    int tid = threadIdx.x, w = tid >> 5, lane = tid & 31;
    size_t r0 = (size_t)blockIdx.x * 32;
    int b  = (int)(r0 >> 11);
    int k0 = (int)(r0 & 2047);

    const float4* pg = (const float4*)gamma;
    const float4* pb = (const float4*)beta;
    float4 g0 = pg[lane], g1 = pg[lane + 32];
    float4 b0 = pb[lane], b1 = pb[lane + 32];

#pragma unroll
    for (int s = 0; s < 4; s++) {
        int kk = w * 4 + s;
        size_t row = r0 + kk;
        const float4* px = (const float4*)(x + row * FF);
        float4 v0 = px[lane], v1 = px[lane + 32];

        float sm = v0.x + v0.y + v0.z + v0.w + v1.x + v1.y + v1.z + v1.w;
        float sq = v0.x*v0.x + v0.y*v0.y + v0.z*v0.z + v0.w*v0.w
                 + v1.x*v1.x + v1.y*v1.y + v1.z*v1.z + v1.w*v1.w;
#pragma unroll
        for (int off = 16; off > 0; off >>= 1) {
            sm += __shfl_xor_sync(0xffffffffu, sm, off);
            sq += __shfl_xor_sync(0xffffffffu, sq, off);
        }
        float mu   = sm * (1.0f / FF);
        float var  = sq * (1.0f / FF) - mu * mu;
        float rstd = rsqrtf(var + 1e-5f);
        float din  = g_rs[row];
        float sinv = (din != 0.f) ? rsqrtf(din) : 0.f;

        float xv[8], gm[8], bt[8], xn[8];
        xv[0]=v0.x; xv[1]=v0.y; xv[2]=v0.z; xv[3]=v0.w; xv[4]=v1.x; xv[5]=v1.y; xv[6]=v1.z; xv[7]=v1.w;
        gm[0]=g0.x; gm[1]=g0.y; gm[2]=g0.z; gm[3]=g0.w; gm[4]=g1.x; gm[5]=g1.y; gm[6]=g1.z; gm[7]=g1.w;
        bt[0]=b0.x; bt[1]=b0.y; bt[2]=b0.z; bt[3]=b0.w; bt[4]=b1.x; bt[5]=b1.y; bt[6]=b1.z; bt[7]=b1.w;

#pragma unroll
        for (int j = 0; j < 8; j++) {
            xn[j] = (xv[j] - mu) * rstd * gm[j] + bt[j];
            int n = (j < 4) ? (lane * 4 + j) : (128 + lane * 4 + j - 4);
            tr[n * 37 + kk] = sinv * xn[j];
        }
        __half2 p0 = __floats2half2_rn(xn[0], xn[1]);
        __half2 p1 = __floats2half2_rn(xn[2], xn[3]);
        __half2 p2 = __floats2half2_rn(xn[4], xn[5]);
        __half2 p3 = __floats2half2_rn(xn[6], xn[7]);
        __half* dst = g_xnh + row * FF;
        *(uint2*)(dst + lane * 4)       = make_uint2(h2u(p0), h2u(p1));
        *(uint2*)(dst + 128 + lane * 4) = make_uint2(h2u(p2), h2u(p3));
    }
    __syncthreads();

    int fsub = tid >> 2;
    int kc   = (tid & 3) * 8;
    __half* dbase = g_xshT + (size_t)b * FF * NN + k0 + kc;
#pragma unroll
    for (int pass = 0; pass < 4; pass++) {
        int f = pass * 64 + fsub;
        const float* src = &tr[f * 37 + kc];
        uint4 o;
        o.x = h2u(__floats2half2_rn(src[0], src[1]));
        o.y = h2u(__floats2half2_rn(src[2], src[3]));
        o.z = h2u(__floats2half2_rn(src[4], src[5]));
        o.w = h2u(__floats2half2_rn(src[6], src[7]));
        *(uint4*)(dbase + (size_t)f * NN) = o;
    }
}

// ---------------- GEMM core: reg-double-buffered LDSM/MMA overlap ----------------
__device__ __forceinline__ void gemm_tile(float (&acc)[2][8][4],
                                          uint32_t Abase, uint32_t Bbase,
                                          uint32_t aoff, uint32_t boff) {
    uint32_t a[2][2][4], bp[2][4][4];
    ldsm4(a[0][0], Abase + aoff);
    ldsm4(a[0][1], Abase + aoff + 16 * APADH * 2);
#pragma unroll
    for (int p = 0; p < 4; p++)
        ldsm4(bp[0][p], Bbase + boff + p * 16 * BPADH * 2);

#pragma unroll
    for (int ks = 0; ks < 4; ks++) {
        int cur = ks & 1, nxt = cur ^ 1;
        if (ks < 3) {
            uint32_t kb = (ks + 1) * 32;
            ldsm4(a[nxt][0], Abase + aoff + kb);
            ldsm4(a[nxt][1], Abase + aoff + 16 * APADH * 2 + kb);
#pragma unroll
            for (int p = 0; p < 4; p++)
                ldsm4(bp[nxt][p], Bbase + boff + p * 16 * BPADH * 2 + kb);
        }
#pragma unroll
        for (int tm = 0; tm < 2; tm++)
#pragma unroll
            for (int nt = 0; nt < 8; nt++) {
                uint32_t bb[2] = { bp[cur][nt >> 1][nt & 1], bp[cur][nt >> 1][2 + (nt & 1)] };
                mma_f16(acc[tm][nt], a[cur][tm], bb);
            }
    }
}

// ---------------- GEMM1: g_zh[b] = -s_out * (adjh[b] @ xs[b]) ----------------
__global__ void __launch_bounds__(NTH, 2) gemm1_kernel() {
    extern __shared__ __half sh[];
    uint32_t sAu = (uint32_t)__cvta_generic_to_shared(sh);
    uint32_t sBu = sAu + NSTAGE * A_TILE_H * 2;

    int b  = blockIdx.z;
    int m0 = blockIdx.x * BM;
    int n0 = blockIdx.y * BN;
    const __half* A  = g_adjh + (size_t)(b * NN + m0) * NN;
    const __half* Bt = g_xshT + (size_t)b * FF * NN + (size_t)n0 * NN;

    int tid = threadIdx.x, warp = tid >> 5, lane = tid & 31;
    int wm = warp >> 1, wn = warp & 1;
    int g = lane >> 2, tg = lane & 3;

    uint32_t aoff = ((wm * 32 + (lane & 15)) * APADH) * 2 + (lane >> 4) * 16;
    uint32_t boff = ((wn * 64 + (lane & 15)) * BPADH) * 2 + (lane >> 4) * 16;

    float acc[2][8][4];
#pragma unroll
    for (int i = 0; i < 2; i++)
#pragma unroll
        for (int j = 0; j < 8; j++)
#pragma unroll
            for (int k = 0; k < 4; k++) acc[i][j][k] = 0.f;

    auto load = [&](int kt, int buf) {
        int k0 = kt * BK;
        uint32_t Ad = sAu + buf * A_TILE_H * 2;
        uint32_t Bd = sBu + buf * B_TILE_H * 2;
#pragma unroll
        for (int l = 0; l < 4; l++) {
            int idx = tid + l * NTH;
            int ar = idx >> 3, ac8 = (idx & 7) * 8;
            cp16(Ad + (ar * APADH + ac8) * 2, A + (size_t)ar * NN + k0 + ac8);
        }
#pragma unroll
        for (int l = 0; l < 4; l++) {
            int idx = tid + l * NTH;
            int br = idx >> 3, bc8 = (idx & 7) * 8;
            cp16(Bd + (br * BPADH + bc8) * 2, Bt + (size_t)br * NN + k0 + bc8);
        }
    };

    const int KT = NN / BK;   // 32
    load(0, 0); CP_COMMIT();
    load(1, 1); CP_COMMIT();

    for (int kt = 0; kt < KT; kt++) {
        CP_WAIT(1);
        __syncthreads();
        if (kt + 2 < KT) load(kt + 2, (kt + 2) % NSTAGE);
        CP_COMMIT();
        int buf = kt % NSTAGE;
        gemm_tile(acc, sAu + buf * A_TILE_H * 2, sBu + buf * B_TILE_H * 2, aoff, boff);
    }

    const float* cb = g_cs + (size_t)b * NN;
#pragma unroll
    for (int tm = 0; tm < 2; tm++) {
        int rl = m0 + wm * 32 + tm * 16 + g;
        float c0v = cb[rl], c1v = cb[rl + 8];
        float sc0 = (c0v != 0.f) ? -rsqrtf(c0v) : 0.f;
        float sc1 = (c1v != 0.f) ? -rsqrtf(c1v) : 0.f;
        __half* z0 = g_zh + ((size_t)b * NN + rl)     * FF + n0;
        __half* z1 = g_zh + ((size_t)b * NN + rl + 8) * FF + n0;
#pragma unroll
        for (int nt = 0; nt < 8; nt++) {
            int c = wn * 64 + nt * 8 + tg * 2;
            *(uint32_t*)(z0 + c) = h2u(__floats2half2_rn(acc[tm][nt][0]*sc0, acc[tm][nt][1]*sc0));
            *(uint32_t*)(z1 + c) = h2u(__floats2half2_rn(acc[tm][nt][2]*sc1, acc[tm][nt][3]*sc1));
        }
    }
}

// ---------------- GEMM2: out = softplus([xn|z] @ [Wsum;Wn]) ----------------
__global__ void __launch_bounds__(NTH, 2) gemm2_kernel(float* __restrict__ out) {
    extern __shared__ __half sh[];
    uint32_t sAu = (uint32_t)__cvta_generic_to_shared(sh);
    uint32_t sBu = sAu + NSTAGE * A_TILE_H * 2;

    int m0 = blockIdx.x * BM;
    int n0 = blockIdx.y * BN;
    int tid = threadIdx.x, warp = tid >> 5, lane = tid & 31;
    int wm = warp >> 1, wn = warp & 1;
    int g = lane >> 2, tg = lane & 3;

    uint32_t aoff = ((wm * 32 + (lane & 15)) * APADH) * 2 + (lane >> 4) * 16;
    uint32_t boff = ((wn * 64 + (lane & 15)) * BPADH) * 2 + (lane >> 4) * 16;

    float acc[2][8][4];
#pragma unroll
    for (int i = 0; i < 2; i++)
#pragma unroll
        for (int j = 0; j < 8; j++)
#pragma unroll
            for (int k = 0; k < 4; k++) acc[i][j][k] = 0.f;

    auto load = [&](int kt, int buf) {
        int kk0 = kt * BK;
        const __half* Asrc = (kk0 < FF) ? g_xnh : g_zh;
        const __half* Bsrc = g_wT + ((kk0 < FF) ? 0 : FF * OO);
        int kc = (kk0 < FF) ? kk0 : (kk0 - FF);
        uint32_t Ad = sAu + buf * A_TILE_H * 2;
        uint32_t Bd = sBu + buf * B_TILE_H * 2;
#pragma unroll
        for (int l = 0; l < 4; l++) {
            int idx = tid + l * NTH;
            int ar = idx >> 3, ac8 = (idx & 7) * 8;
            cp16(Ad + (ar * APADH + ac8) * 2, Asrc + (size_t)(m0 + ar) * FF + kc + ac8);
        }
#pragma unroll
        for (int l = 0; l < 4; l++) {
            int idx = tid + l * NTH;
            int br = idx >> 3, bc8 = (idx & 7) * 8;
            cp16(Bd + (br * BPADH + bc8) * 2, Bsrc + (size_t)(n0 + br) * FF + kc + bc8);
        }
    };

    const int KT = (2 * FF) / BK;   // 8
    load(0, 0); CP_COMMIT();
    load(1, 1); CP_COMMIT();

    for (int kt = 0; kt < KT; kt++) {
        CP_WAIT(1);
        __syncthreads();
        if (kt + 2 < KT) load(kt + 2, (kt + 2) % NSTAGE);
        CP_COMMIT();
        int buf = kt % NSTAGE;
        gemm_tile(acc, sAu + buf * A_TILE_H * 2, sBu + buf * B_TILE_H * 2, aoff, boff);
    }

#pragma unroll
    for (int tm = 0; tm < 2; tm++) {
#pragma unroll
        for (int nt = 0; nt < 8; nt++) {
            int r = m0 + wm * 32 + tm * 16 + g;
            int c = n0 + wn * 64 + nt * 8 + tg * 2;
            float2 v0 = make_float2(softplus_f(acc[tm][nt][0]), softplus_f(acc[tm][nt][1]));
            float2 v1 = make_float2(softplus_f(acc[tm][nt][2]), softplus_f(acc[tm][nt][3]));
            *(float2*)&out[(size_t)r * OO + c]       = v0;
            *(float2*)&out[(size_t)(r + 8) * OO + c] = v1;
        }
    }
}

// ---------------- launch (gemm1 in profiler slot #4) ----------------
extern "C" void kernel_launch(void* const* d_in, const int* in_sizes, int n_in,
                              void* d_out, int out_size) {
    const float* x      = (const float*)d_in[0];
    const float* adj    = (const float*)d_in[1];
    const float* gamma  = (const float*)d_in[2];
    const float* beta   = (const float*)d_in[3];
    const float* Wself  = (const float*)d_in[4];
    const float* Wneigh = (const float*)d_in[5];
    float* out = (float*)d_out;

    cudaFuncSetAttribute(gemm1_kernel, cudaFuncAttributeMaxDynamicSharedMemorySize, SMEM_BYTES);
    cudaFuncSetAttribute(gemm2_kernel, cudaFuncAttributeMaxDynamicSharedMemorySize, SMEM_BYTES);

    prep_kernel<<<128, 256>>>(Wself, Wneigh);
    degree_kernel<<<ROWS / 8, 256>>>(adj);
    ln_kernel<<<ROWS / 32, 256>>>(x, gamma, beta);
    gemm1_kernel<<<dim3(NN / BM, FF / BN, BATCH), NTH, SMEM_BYTES>>>();
    gemm2_kernel<<<dim3(ROWS / BM, OO / BN), NTH, SMEM_BYTES>>>(out);
}

// round 17
// speedup vs baseline: 1.1016x; 1.1016x over previous
#include <cuda_runtime.h>
#include <cuda_fp16.h>
#include <cstdint>
#include <math.h>

#define BATCH 8
#define NN    2048
#define FF    256
#define OO    256
#define ROWS  (BATCH*NN)   /* 16384 */

// GEMM tiling: 128x128 CTA tile, K-step 64, 256 threads, fp16, 3-stage, 2 CTAs/SM
#define BM 128
#define BN 128
#define BK 64
#define NTH 256
#define APADH 72
#define BPADH 72
#define A_TILE_H (BM*APADH)
#define B_TILE_H (BN*BPADH)
#define NSTAGE 3
#define SMEM_BYTES (NSTAGE*(A_TILE_H+B_TILE_H)*2)   /* 110592 B */

// ---------------- scratch ----------------
__device__ float  g_rs  [ROWS];
__device__ float  g_cs  [ROWS];
__device__ __half g_adjh[(size_t)BATCH*NN*NN];
__device__ __half g_xnh [ROWS*FF];
__device__ __half g_xshT[ROWS*FF];       // [b][f][n]
__device__ __half g_zh  [ROWS*FF];
__device__ __half g_wT  [2*FF*OO];       // [0]=(Ws+Wn)^T, [1]=Wn^T, [o][k]

// ---------------- helpers ----------------
__device__ __forceinline__ uint32_t h2u(__half2 h) {
    return *reinterpret_cast<uint32_t*>(&h);
}
__device__ __forceinline__ float softplus_f(float x) {
    return fmaxf(x, 0.0f) + log1pf(expf(-fabsf(x)));
}
__device__ __forceinline__ void cp16(uint32_t dst, const void* src) {
    asm volatile("cp.async.cg.shared.global [%0], [%1], 16;\n" :: "r"(dst), "l"(src));
}
#define CP_COMMIT() asm volatile("cp.async.commit_group;\n" ::: "memory")
#define CP_WAIT(n)  asm volatile("cp.async.wait_group %0;\n" :: "n"(n) : "memory")

__device__ __forceinline__ void mma_f16(float (&d)[4], const uint32_t (&a)[4], const uint32_t (&b)[2]) {
    asm volatile(
        "mma.sync.aligned.m16n8k16.row.col.f32.f16.f16.f32 "
        "{%0,%1,%2,%3}, {%4,%5,%6,%7}, {%8,%9}, {%0,%1,%2,%3};\n"
        : "+f"(d[0]), "+f"(d[1]), "+f"(d[2]), "+f"(d[3])
        : "r"(a[0]), "r"(a[1]), "r"(a[2]), "r"(a[3]), "r"(b[0]), "r"(b[1]));
}
__device__ __forceinline__ void ldsm4(uint32_t (&r)[4], uint32_t addr) {
    asm volatile("ldmatrix.sync.aligned.m8n8.x4.shared.b16 {%0,%1,%2,%3}, [%4];"
                 : "=r"(r[0]), "=r"(r[1]), "=r"(r[2]), "=r"(r[3]) : "r"(addr));
}
__device__ __forceinline__ float4 ldcs4(const float* p) {
    float4 v;
    asm volatile("ld.global.cs.v4.f32 {%0,%1,%2,%3}, [%4];"
                 : "=f"(v.x), "=f"(v.y), "=f"(v.z), "=f"(v.w) : "l"(p));
    return v;
}

// ---------------- fused prep: zero g_cs + transpose weights ----------------
__global__ void __launch_bounds__(256) prep_kernel(const float* __restrict__ Ws,
                                                   const float* __restrict__ Wn) {
    if (blockIdx.x < 64) {
        g_cs[blockIdx.x * 256 + threadIdx.x] = 0.f;
        return;
    }
    __shared__ float t1[32][33], t2[32][33];
    int bid = blockIdx.x - 64;                 // 0..63
    int tx = threadIdx.x & 31, ty = threadIdx.x >> 5;
    int k0 = (bid & 7) * 32, o0 = (bid >> 3) * 32;
#pragma unroll
    for (int i = 0; i < 4; i++) {
        int k = k0 + ty + i * 8;
        float wn = Wn[(size_t)k * OO + o0 + tx];
        float ws = Ws[(size_t)k * OO + o0 + tx];
        t1[ty + i * 8][tx] = ws + wn;
        t2[ty + i * 8][tx] = wn;
    }
    __syncthreads();
#pragma unroll
    for (int i = 0; i < 4; i++) {
        int o = o0 + ty + i * 8;
        g_wT[(size_t)o * FF + k0 + tx]           = __float2half_rn(t1[tx][ty + i * 8]);
        g_wT[FF * OO + (size_t)o * FF + k0 + tx] = __float2half_rn(t2[tx][ty + i * 8]);
    }
}

// ---------------- fused degree + fp16-convert (round-15 exact: 16 rows/block) ----------------
__global__ void __launch_bounds__(256) degree_kernel(const float* __restrict__ adj) {
    __shared__ float rowpart[16][9];
    int tid = threadIdx.x, lane = tid & 31, w = tid >> 5;
    size_t r0 = (size_t)blockIdx.x * 16;
    const float* base = adj + r0 * NN;
    int c0 = tid * 4;

    float cs[8] = {0,0,0,0,0,0,0,0};
#pragma unroll 8
    for (int rr = 0; rr < 16; rr++) {
        float4 v0 = ldcs4(base + (size_t)rr * NN + c0);
        float4 v1 = ldcs4(base + (size_t)rr * NN + c0 + 1024);
        __half2 h0 = __floats2half2_rn(v0.x, v0.y);
        __half2 h1 = __floats2half2_rn(v0.z, v0.w);
        __half2 h2 = __floats2half2_rn(v1.x, v1.y);
        __half2 h3 = __floats2half2_rn(v1.z, v1.w);
        __half* hd = g_adjh + (r0 + rr) * NN;
        *(uint2*)(hd + c0)        = make_uint2(h2u(h0), h2u(h1));
        *(uint2*)(hd + c0 + 1024) = make_uint2(h2u(h2), h2u(h3));

        cs[0] += v0.x; cs[1] += v0.y; cs[2] += v0.z; cs[3] += v0.w;
        cs[4] += v1.x; cs[5] += v1.y; cs[6] += v1.z; cs[7] += v1.w;
        float rs = v0.x + v0.y + v0.z + v0.w + v1.x + v1.y + v1.z + v1.w;
#pragma unroll
        for (int off = 16; off > 0; off >>= 1) rs += __shfl_xor_sync(0xffffffffu, rs, off);
        if (lane == 0) rowpart[rr][w] = rs;
    }
    __syncthreads();
    if (tid < 16) {
        float s = 0.f;
#pragma unroll
        for (int j = 0; j < 8; j++) s += rowpart[tid][j];
        g_rs[r0 + tid] = s;
    }
    int b = (int)(r0 >> 11);
    float* cbase = g_cs + (size_t)b * NN;
#pragma unroll
    for (int j = 0; j < 4; j++) atomicAdd(cbase + c0 + j, cs[j]);
#pragma unroll
    for (int j = 0; j < 4; j++) atomicAdd(cbase + c0 + 1024 + j, cs[4 + j]);
}

// ---------------- layernorm (32 rows/block; coalesced transposed write) ----------------
__global__ void __launch_bounds__(256) ln_kernel(const float* __restrict__ x,
                                                 const float* __restrict__ gamma,
                                                 const float* __restrict__ beta) {
    __shared__ float tr[256 * 37];
    int tid = threadIdx.x, w = tid >> 5, lane = tid & 31;
    size_t r0 = (size_t)blockIdx.x * 32;
    int b  = (int)(r0 >> 11);
    int k0 = (int)(r0 & 2047);

    const float4* pg = (const float4*)gamma;
    const float4* pb = (const float4*)beta;
    float4 g0 = pg[lane], g1 = pg[lane + 32];
    float4 b0 = pb[lane], b1 = pb[lane + 32];

#pragma unroll
    for (int s = 0; s < 4; s++) {
        int kk = w * 4 + s;
        size_t row = r0 + kk;
        const float4* px = (const float4*)(x + row * FF);
        float4 v0 = px[lane], v1 = px[lane + 32];

        float sm = v0.x + v0.y + v0.z + v0.w + v1.x + v1.y + v1.z + v1.w;
        float sq = v0.x*v0.x + v0.y*v0.y + v0.z*v0.z + v0.w*v0.w
                 + v1.x*v1.x + v1.y*v1.y + v1.z*v1.z + v1.w*v1.w;
#pragma unroll
        for (int off = 16; off > 0; off >>= 1) {
            sm += __shfl_xor_sync(0xffffffffu, sm, off);
            sq += __shfl_xor_sync(0xffffffffu, sq, off);
        }
        float mu   = sm * (1.0f / FF);
        float var  = sq * (1.0f / FF) - mu * mu;
        float rstd = rsqrtf(var + 1e-5f);
        float din  = g_rs[row];
        float sinv = (din != 0.f) ? rsqrtf(din) : 0.f;

        float xv[8], gm[8], bt[8], xn[8];
        xv[0]=v0.x; xv[1]=v0.y; xv[2]=v0.z; xv[3]=v0.w; xv[4]=v1.x; xv[5]=v1.y; xv[6]=v1.z; xv[7]=v1.w;
        gm[0]=g0.x; gm[1]=g0.y; gm[2]=g0.z; gm[3]=g0.w; gm[4]=g1.x; gm[5]=g1.y; gm[6]=g1.z; gm[7]=g1.w;
        bt[0]=b0.x; bt[1]=b0.y; bt[2]=b0.z; bt[3]=b0.w; bt[4]=b1.x; bt[5]=b1.y; bt[6]=b1.z; bt[7]=b1.w;

#pragma unroll
        for (int j = 0; j < 8; j++) {
            xn[j] = (xv[j] - mu) * rstd * gm[j] + bt[j];
            int n = (j < 4) ? (lane * 4 + j) : (128 + lane * 4 + j - 4);
            tr[n * 37 + kk] = sinv * xn[j];
        }
        __half2 p0 = __floats2half2_rn(xn[0], xn[1]);
        __half2 p1 = __floats2half2_rn(xn[2], xn[3]);
        __half2 p2 = __floats2half2_rn(xn[4], xn[5]);
        __half2 p3 = __floats2half2_rn(xn[6], xn[7]);
        __half* dst = g_xnh + row * FF;
        *(uint2*)(dst + lane * 4)       = make_uint2(h2u(p0), h2u(p1));
        *(uint2*)(dst + 128 + lane * 4) = make_uint2(h2u(p2), h2u(p3));
    }
    __syncthreads();

    int fsub = tid >> 2;
    int kc   = (tid & 3) * 8;
    __half* dbase = g_xshT + (size_t)b * FF * NN + k0 + kc;
#pragma unroll
    for (int pass = 0; pass < 4; pass++) {
        int f = pass * 64 + fsub;
        const float* src = &tr[f * 37 + kc];
        uint4 o;
        o.x = h2u(__floats2half2_rn(src[0], src[1]));
        o.y = h2u(__floats2half2_rn(src[2], src[3]));
        o.z = h2u(__floats2half2_rn(src[4], src[5]));
        o.w = h2u(__floats2half2_rn(src[6], src[7]));
        *(uint4*)(dbase + (size_t)f * NN) = o;
    }
}

// ---------------- GEMM core: reg-double-buffered LDSM/MMA overlap ----------------
__device__ __forceinline__ void gemm_tile(float (&acc)[2][8][4],
                                          uint32_t Abase, uint32_t Bbase,
                                          uint32_t aoff, uint32_t boff) {
    uint32_t a[2][2][4], bp[2][4][4];
    ldsm4(a[0][0], Abase + aoff);
    ldsm4(a[0][1], Abase + aoff + 16 * APADH * 2);
#pragma unroll
    for (int p = 0; p < 4; p++)
        ldsm4(bp[0][p], Bbase + boff + p * 16 * BPADH * 2);

#pragma unroll
    for (int ks = 0; ks < 4; ks++) {
        int cur = ks & 1, nxt = cur ^ 1;
        if (ks < 3) {
            uint32_t kb = (ks + 1) * 32;
            ldsm4(a[nxt][0], Abase + aoff + kb);
            ldsm4(a[nxt][1], Abase + aoff + 16 * APADH * 2 + kb);
#pragma unroll
            for (int p = 0; p < 4; p++)
                ldsm4(bp[nxt][p], Bbase + boff + p * 16 * BPADH * 2 + kb);
        }
#pragma unroll
        for (int tm = 0; tm < 2; tm++)
#pragma unroll
            for (int nt = 0; nt < 8; nt++) {
                uint32_t bb[2] = { bp[cur][nt >> 1][nt & 1], bp[cur][nt >> 1][2 + (nt & 1)] };
                mma_f16(acc[tm][nt], a[cur][tm], bb);
            }
    }
}

// ---------------- GEMM1: g_zh[b] = -s_out * (adjh[b] @ xs[b]) ----------------
__global__ void __launch_bounds__(NTH, 2) gemm1_kernel() {
    extern __shared__ __half sh[];
    uint32_t sAu = (uint32_t)__cvta_generic_to_shared(sh);
    uint32_t sBu = sAu + NSTAGE * A_TILE_H * 2;

    int b  = blockIdx.z;
    int m0 = blockIdx.x * BM;
    int n0 = blockIdx.y * BN;
    const __half* A  = g_adjh + (size_t)(b * NN + m0) * NN;
    const __half* Bt = g_xshT + (size_t)b * FF * NN + (size_t)n0 * NN;

    int tid = threadIdx.x, warp = tid >> 5, lane = tid & 31;
    int wm = warp >> 1, wn = warp & 1;
    int g = lane >> 2, tg = lane & 3;

    uint32_t aoff = ((wm * 32 + (lane & 15)) * APADH) * 2 + (lane >> 4) * 16;
    uint32_t boff = ((wn * 64 + (lane & 15)) * BPADH) * 2 + (lane >> 4) * 16;

    float acc[2][8][4];
#pragma unroll
    for (int i = 0; i < 2; i++)
#pragma unroll
        for (int j = 0; j < 8; j++)
#pragma unroll
            for (int k = 0; k < 4; k++) acc[i][j][k] = 0.f;

    auto load = [&](int kt, int buf) {
        int k0 = kt * BK;
        uint32_t Ad = sAu + buf * A_TILE_H * 2;
        uint32_t Bd = sBu + buf * B_TILE_H * 2;
#pragma unroll
        for (int l = 0; l < 4; l++) {
            int idx = tid + l * NTH;
            int ar = idx >> 3, ac8 = (idx & 7) * 8;
            cp16(Ad + (ar * APADH + ac8) * 2, A + (size_t)ar * NN + k0 + ac8);
        }
#pragma unroll
        for (int l = 0; l < 4; l++) {
            int idx = tid + l * NTH;
            int br = idx >> 3, bc8 = (idx & 7) * 8;
            cp16(Bd + (br * BPADH + bc8) * 2, Bt + (size_t)br * NN + k0 + bc8);
        }
    };

    const int KT = NN / BK;   // 32
    load(0, 0); CP_COMMIT();
    load(1, 1); CP_COMMIT();

    for (int kt = 0; kt < KT; kt++) {
        CP_WAIT(1);
        __syncthreads();
        if (kt + 2 < KT) load(kt + 2, (kt + 2) % NSTAGE);
        CP_COMMIT();
        int buf = kt % NSTAGE;
        gemm_tile(acc, sAu + buf * A_TILE_H * 2, sBu + buf * B_TILE_H * 2, aoff, boff);
    }

    const float* cb = g_cs + (size_t)b * NN;
#pragma unroll
    for (int tm = 0; tm < 2; tm++) {
        int rl = m0 + wm * 32 + tm * 16 + g;
        float c0v = cb[rl], c1v = cb[rl + 8];
        float sc0 = (c0v != 0.f) ? -rsqrtf(c0v) : 0.f;
        float sc1 = (c1v != 0.f) ? -rsqrtf(c1v) : 0.f;
        __half* z0 = g_zh + ((size_t)b * NN + rl)     * FF + n0;
        __half* z1 = g_zh + ((size_t)b * NN + rl + 8) * FF + n0;
#pragma unroll
        for (int nt = 0; nt < 8; nt++) {
            int c = wn * 64 + nt * 8 + tg * 2;
            *(uint32_t*)(z0 + c) = h2u(__floats2half2_rn(acc[tm][nt][0]*sc0, acc[tm][nt][1]*sc0));
            *(uint32_t*)(z1 + c) = h2u(__floats2half2_rn(acc[tm][nt][2]*sc1, acc[tm][nt][3]*sc1));
        }
    }
}

// ---------------- GEMM2: out = softplus([xn|z] @ [Wsum;Wn]) ----------------
__global__ void __launch_bounds__(NTH, 2) gemm2_kernel(float* __restrict__ out) {
    extern __shared__ __half sh[];
    uint32_t sAu = (uint32_t)__cvta_generic_to_shared(sh);
    uint32_t sBu = sAu + NSTAGE * A_TILE_H * 2;

    int m0 = blockIdx.x * BM;
    int n0 = blockIdx.y * BN;
    int tid = threadIdx.x, warp = tid >> 5, lane = tid & 31;
    int wm = warp >> 1, wn = warp & 1;
    int g = lane >> 2, tg = lane & 3;

    uint32_t aoff = ((wm * 32 + (lane & 15)) * APADH) * 2 + (lane >> 4) * 16;
    uint32_t boff = ((wn * 64 + (lane & 15)) * BPADH) * 2 + (lane >> 4) * 16;

    float acc[2][8][4];
#pragma unroll
    for (int i = 0; i < 2; i++)
#pragma unroll
        for (int j = 0; j < 8; j++)
#pragma unroll
            for (int k = 0; k < 4; k++) acc[i][j][k] = 0.f;

    auto load = [&](int kt, int buf) {
        int kk0 = kt * BK;
        const __half* Asrc = (kk0 < FF) ? g_xnh : g_zh;
        const __half* Bsrc = g_wT + ((kk0 < FF) ? 0 : FF * OO);
        int kc = (kk0 < FF) ? kk0 : (kk0 - FF);
        uint32_t Ad = sAu + buf * A_TILE_H * 2;
        uint32_t Bd = sBu + buf * B_TILE_H * 2;
#pragma unroll
        for (int l = 0; l < 4; l++) {
            int idx = tid + l * NTH;
            int ar = idx >> 3, ac8 = (idx & 7) * 8;
            cp16(Ad + (ar * APADH + ac8) * 2, Asrc + (size_t)(m0 + ar) * FF + kc + ac8);
        }
#pragma unroll
        for (int l = 0; l < 4; l++) {
            int idx = tid + l * NTH;
            int br = idx >> 3, bc8 = (idx & 7) * 8;
            cp16(Bd + (br * BPADH + bc8) * 2, Bsrc + (size_t)(n0 + br) * FF + kc + bc8);
        }
    };

    const int KT = (2 * FF) / BK;   // 8
    load(0, 0); CP_COMMIT();
    load(1, 1); CP_COMMIT();

    for (int kt = 0; kt < KT; kt++) {
        CP_WAIT(1);
        __syncthreads();
        if (kt + 2 < KT) load(kt + 2, (kt + 2) % NSTAGE);
        CP_COMMIT();
        int buf = kt % NSTAGE;
        gemm_tile(acc, sAu + buf * A_TILE_H * 2, sBu + buf * B_TILE_H * 2, aoff, boff);
    }

#pragma unroll
    for (int tm = 0; tm < 2; tm++) {
#pragma unroll
        for (int nt = 0; nt < 8; nt++) {
            int r = m0 + wm * 32 + tm * 16 + g;
            int c = n0 + wn * 64 + nt * 8 + tg * 2;
            float2 v0 = make_float2(softplus_f(acc[tm][nt][0]), softplus_f(acc[tm][nt][1]));
            float2 v1 = make_float2(softplus_f(acc[tm][nt][2]), softplus_f(acc[tm][nt][3]));
            *(float2*)&out[(size_t)r * OO + c]       = v0;
            *(float2*)&out[(size_t)(r + 8) * OO + c] = v1;
        }
    }
}

// ---------------- launch ----------------
extern "C" void kernel_launch(void* const* d_in, const int* in_sizes, int n_in,
                              void* d_out, int out_size) {
    const float* x      = (const float*)d_in[0];
    const float* adj    = (const float*)d_in[1];
    const float* gamma  = (const float*)d_in[2];
    const float* beta   = (const float*)d_in[3];
    const float* Wself  = (const float*)d_in[4];
    const float* Wneigh = (const float*)d_in[5];
    float* out = (float*)d_out;

    cudaFuncSetAttribute(gemm1_kernel, cudaFuncAttributeMaxDynamicSharedMemorySize, SMEM_BYTES);
    cudaFuncSetAttribute(gemm2_kernel, cudaFuncAttributeMaxDynamicSharedMemorySize, SMEM_BYTES);

    prep_kernel<<<128, 256>>>(Wself, Wneigh);
    degree_kernel<<<ROWS / 16, 256>>>(adj);
    ln_kernel<<<ROWS / 32, 256>>>(x, gamma, beta);
    gemm1_kernel<<<dim3(NN / BM, FF / BN, BATCH), NTH, SMEM_BYTES>>>();
    gemm2_kernel<<<dim3(ROWS / BM, OO / BN), NTH, SMEM_BYTES>>>(out);
}